// round 5
// baseline (speedup 1.0000x reference)
#include <cuda_runtime.h>

#define S_NODES 8192
#define NN      8384
#define CH      128
#define BB      2
#define EE      262144

// ---------------- scratch (device globals; no allocation allowed) -----------
__device__ float g_h0[BB * NN * CH];
__device__ float g_h1[BB * NN * CH];
__device__ float g_q[BB * NN];
__device__ float g_p[BB * NN];
__device__ float g_dinvI[BB * NN];      // gcn norm: rsqrt(intra_in_deg + 1)
__device__ float g_dinvX[BB * NN];      // inter: 1/deg or 0
__device__ int   g_cntI[BB * NN];
__device__ int   g_cntX[BB * NN];
__device__ int   g_posI[BB * NN];
__device__ int   g_posX[BB * NN];
__device__ int   g_rpI[BB * (NN + 1)];  // intra CSR rowptr
__device__ int   g_rpX[BB * (NN + 1)];  // inter CSR rowptr
__device__ int   g_srcI[BB * EE];
__device__ int   g_srcX[BB * EE];
__device__ int   g_dstI[BB * EE];
__device__ int   g_dstX[BB * EE];
__device__ int2  g_scI[BB * EE];        // packed (src, coef) per slot
__device__ int2  g_scX[BB * EE];

__device__ __forceinline__ float tanh_fast(float z) {
    float az = fabsf(z);
    float e  = __expf(2.0f * az);
    float r  = 1.0f - 2.0f / (e + 1.0f);
    return copysignf(r, z);
}

// ---------------- CSR build ------------------------------------------------
__global__ void k_zero() {
    int i = blockIdx.x * blockDim.x + threadIdx.x;
    if (i < BB * NN) { g_cntI[i] = 0; g_cntX[i] = 0; g_posI[i] = 0; g_posX[i] = 0; }
}

__global__ void k_hist(const int* __restrict__ ei) {
    int i = blockIdx.x * blockDim.x + threadIdx.x;
    if (i >= BB * EE) return;
    int b = i / EE, e = i - b * EE;
    int s = ei[b * 2 * EE + e];
    int d = ei[b * 2 * EE + EE + e];
    bool intra = (s < S_NODES) == (d < S_NODES);
    if (intra) atomicAdd(&g_cntI[b * NN + d], 1);
    else       atomicAdd(&g_cntX[b * NN + d], 1);
}

// one block per batch: exclusive scans of cntI and cntX over NN nodes + dinv
__global__ void k_scan() {
    __shared__ int shI[1024];
    __shared__ int shX[1024];
    __shared__ int carryI, carryX;
    int b = blockIdx.x;
    if (threadIdx.x == 0) { carryI = 0; carryX = 0; }
    __syncthreads();
    for (int base = 0; base < NN; base += 1024) {
        int i = base + threadIdx.x;
        int cI = 0, cX = 0;
        if (i < NN) {
            cI = g_cntI[b * NN + i];
            cX = g_cntX[b * NN + i];
        }
        shI[threadIdx.x] = cI;
        shX[threadIdx.x] = cX;
        __syncthreads();
        for (int off = 1; off < 1024; off <<= 1) {
            int tI = (threadIdx.x >= off) ? shI[threadIdx.x - off] : 0;
            int tX = (threadIdx.x >= off) ? shX[threadIdx.x - off] : 0;
            __syncthreads();
            shI[threadIdx.x] += tI;
            shX[threadIdx.x] += tX;
            __syncthreads();
        }
        if (i < NN) {
            g_rpI[b * (NN + 1) + i] = carryI + shI[threadIdx.x] - cI;  // exclusive
            g_rpX[b * (NN + 1) + i] = carryX + shX[threadIdx.x] - cX;
            g_dinvI[b * NN + i] = rsqrtf((float)(cI + 1));
            g_dinvX[b * NN + i] = (cX > 0) ? (1.0f / (float)cX) : 0.0f;
        }
        __syncthreads();
        if (threadIdx.x == 1023) { carryI += shI[1023]; carryX += shX[1023]; }
        __syncthreads();
    }
    if (threadIdx.x == 0) {
        g_rpI[b * (NN + 1) + NN] = carryI;
        g_rpX[b * (NN + 1) + NN] = carryX;
    }
}

__global__ void k_scatter(const int* __restrict__ ei) {
    int i = blockIdx.x * blockDim.x + threadIdx.x;
    if (i >= BB * EE) return;
    int b = i / EE, e = i - b * EE;
    int s = ei[b * 2 * EE + e];
    int d = ei[b * 2 * EE + EE + e];
    bool intra = (s < S_NODES) == (d < S_NODES);
    if (intra) {
        int pos = g_rpI[b * (NN + 1) + d] + atomicAdd(&g_posI[b * NN + d], 1);
        g_srcI[b * EE + pos] = s;
        g_dstI[b * EE + pos] = d;
    } else {
        int pos = g_rpX[b * (NN + 1) + d] + atomicAdd(&g_posX[b * NN + d], 1);
        g_srcX[b * EE + pos] = s;
        g_dstX[b * EE + pos] = d;
    }
}

// sort each node's src segment by value -> deterministic FP accumulation order
// (duplicate src values contribute bitwise-identical terms, so value-sort is
//  a deterministic total order for the sum). dst entries are constant within
//  a segment, so only srcs need permuting.
__global__ void k_sort() {
    __shared__ int buf[96 * 128];   // 48 KB, interleaved per thread
    int n = blockIdx.x * blockDim.x + threadIdx.x;
    if (n >= 2 * BB * NN) return;
    bool intra = n < BB * NN;
    int m = intra ? n : n - BB * NN;
    int b = m / NN, v = m - b * NN;
    const int* rp = intra ? g_rpI : g_rpX;
    int* srcs = (intra ? g_srcI : g_srcX) + b * EE;
    int beg = rp[b * (NN + 1) + v];
    int len = rp[b * (NN + 1) + v + 1] - beg;
    if (len <= 1) return;
#define AA(k) buf[(k) * 128 + threadIdx.x]
    if (len <= 96) {
        for (int i = 0; i < len; i++) AA(i) = srcs[beg + i];
        for (int i = 1; i < len; i++) {
            int key = AA(i); int j = i - 1;
            while (j >= 0 && AA(j) > key) { AA(j + 1) = AA(j); j--; }
            AA(j + 1) = key;
        }
        for (int i = 0; i < len; i++) srcs[beg + i] = AA(i);
    } else {  // extremely rare fallback
        for (int i = 1; i < len; i++) {
            int key = srcs[beg + i]; int j = i - 1;
            while (j >= 0 && srcs[beg + j] > key) { srcs[beg + j + 1] = srcs[beg + j]; j--; }
            srcs[beg + j + 1] = key;
        }
    }
#undef AA
}

// ---------------- per-node attention dots: q[v]=x·Wa, p[v]=x·Wb ------------
__global__ void k_dots(const float* __restrict__ x,
                       const float* __restrict__ WaS, const float* __restrict__ WbS,
                       const float* __restrict__ WaT, const float* __restrict__ WbT) {
    int t = blockIdx.x * blockDim.x + threadIdx.x;
    int w = t >> 5, lane = t & 31;
    if (w >= BB * NN) return;
    int v = w % NN;
    const float* Wa = (v < S_NODES) ? WaS : WaT;
    const float* Wb = (v < S_NODES) ? WbS : WbT;
    float4 xv = ((const float4*)x)[w * 32 + lane];
    float4 wa = ((const float4*)Wa)[lane];
    float4 wb = ((const float4*)Wb)[lane];
    float qs = xv.x * wa.x + xv.y * wa.y + xv.z * wa.z + xv.w * wa.w;
    float ps = xv.x * wb.x + xv.y * wb.y + xv.z * wb.z + xv.w * wb.w;
    #pragma unroll
    for (int o = 16; o > 0; o >>= 1) {
        qs += __shfl_xor_sync(0xffffffffu, qs, o);
        ps += __shfl_xor_sync(0xffffffffu, ps, o);
    }
    if (lane == 0) { g_q[w] = qs; g_p[w] = ps; }
}

// ---------------- per-pass edge coefficients into CSR order ----------------
// coef = tanh(q[dst] + p[src]) * norm, packed next to src for the gather.
template <bool INTRA>
__global__ void k_coef() {
    int i = blockIdx.x * blockDim.x + threadIdx.x;
    if (i >= BB * EE) return;
    int b = i / EE, e = i - b * EE;
    int cnt = INTRA ? g_rpI[b * (NN + 1) + NN] : g_rpX[b * (NN + 1) + NN];
    if (e >= cnt) return;
    int slot = b * EE + e;
    int s = INTRA ? g_srcI[slot] : g_srcX[slot];
    int d = INTRA ? g_dstI[slot] : g_dstX[slot];
    int sn = b * NN + s, dn = b * NN + d;
    float z = tanh_fast(g_q[dn] + g_p[sn]);
    float c = INTRA ? z * g_dinvI[sn] * g_dinvI[dn] : z * g_dinvX[dn];
    int2 pk = make_int2(s, __float_as_int(c));
    if (INTRA) g_scI[slot] = pk; else g_scX[slot] = pk;
}

// ---------------- gather (warp per dst node, float4 per lane) --------------
template <bool INTRA, bool RELU>
__global__ void k_gather(const float* __restrict__ xin, float* __restrict__ xout) {
    int t = blockIdx.x * blockDim.x + threadIdx.x;
    int w = t >> 5, lane = t & 31;
    if (w >= BB * NN) return;
    int b = w / NN;
    int v = w - b * NN;
    const float4* __restrict__ x4 = (const float4*)xin;
    float4 xv = x4[w * 32 + lane];
    float4 acc = make_float4(0.f, 0.f, 0.f, 0.f);

    const int* rp = INTRA ? g_rpI : g_rpX;
    int beg = rp[b * (NN + 1) + v];
    int end = rp[b * (NN + 1) + v + 1];
    const int2* __restrict__ sc = (INTRA ? g_scI : g_scX) + b * EE;
    int bNN = b * NN;

    int e = beg;
    for (; e + 4 <= end; e += 4) {
        int2 p0 = sc[e], p1 = sc[e + 1], p2 = sc[e + 2], p3 = sc[e + 3];
        float4 a0 = x4[(bNN + p0.x) * 32 + lane];
        float4 a1 = x4[(bNN + p1.x) * 32 + lane];
        float4 a2 = x4[(bNN + p2.x) * 32 + lane];
        float4 a3 = x4[(bNN + p3.x) * 32 + lane];
        float c0 = __int_as_float(p0.y), c1 = __int_as_float(p1.y);
        float c2 = __int_as_float(p2.y), c3 = __int_as_float(p3.y);
        acc.x += c0 * a0.x; acc.y += c0 * a0.y; acc.z += c0 * a0.z; acc.w += c0 * a0.w;
        acc.x += c1 * a1.x; acc.y += c1 * a1.y; acc.z += c1 * a1.z; acc.w += c1 * a1.w;
        acc.x += c2 * a2.x; acc.y += c2 * a2.y; acc.z += c2 * a2.z; acc.w += c2 * a2.w;
        acc.x += c3 * a3.x; acc.y += c3 * a3.y; acc.z += c3 * a3.z; acc.w += c3 * a3.w;
    }
    for (; e < end; e++) {
        int2 pe = sc[e];
        float ce = __int_as_float(pe.y);
        float4 xs = x4[(bNN + pe.x) * 32 + lane];
        acc.x += ce * xs.x; acc.y += ce * xs.y;
        acc.z += ce * xs.z; acc.w += ce * xs.w;
    }
    if (INTRA) {  // self loop: alpha_self = tanh(q+p), norm = 1/deg = dinv^2
        float dv = g_dinvI[w];
        float cs = tanh_fast(g_q[w] + g_p[w]) * dv * dv;
        acc.x += cs * xv.x; acc.y += cs * xv.y;
        acc.z += cs * xv.z; acc.w += cs * xv.w;
    }
    float4 o;
    o.x = xv.x + acc.x; o.y = xv.y + acc.y;
    o.z = xv.z + acc.z; o.w = xv.w + acc.w;
    if (RELU) {
        o.x = fmaxf(o.x, 0.f); o.y = fmaxf(o.y, 0.f);
        o.z = fmaxf(o.z, 0.f); o.w = fmaxf(o.w, 0.f);
    }
    ((float4*)xout)[w * 32 + lane] = o;
}

// ---------------- launch ---------------------------------------------------
extern "C" void kernel_launch(void* const* d_in, const int* in_sizes, int n_in,
                              void* d_out, int out_size) {
    const float* x   = (const float*)d_in[0];
    const int*   ei  = (const int*)d_in[1];
    const float* Wss = (const float*)d_in[2];
    const float* Wtt = (const float*)d_in[3];
    const float* Wst = (const float*)d_in[4];
    const float* Wts = (const float*)d_in[5];
    float* out = (float*)d_out;

    float *h0, *h1;
    cudaGetSymbolAddress((void**)&h0, g_h0);
    cudaGetSymbolAddress((void**)&h1, g_h1);

    // CSR build (depends only on edge_index; recomputed every call)
    k_zero<<<(BB * NN + 255) / 256, 256>>>();
    k_hist<<<(BB * EE + 255) / 256, 256>>>(ei);
    k_scan<<<BB, 1024>>>();
    k_scatter<<<(BB * EE + 255) / 256, 256>>>(ei);
    k_sort<<<(2 * BB * NN + 127) / 128, 128>>>();

    int ng = (BB * NN * 32 + 255) / 256;   // warp-per-node grids
    int ne = (BB * EE + 255) / 256;        // edge-parallel grids

    // pass 0: intra, layer 0, relu   (W_ss / W_tt row 0)
    k_dots<<<ng, 256>>>(x, Wss, Wss + 128, Wtt, Wtt + 128);
    k_coef<true><<<ne, 256>>>();
    k_gather<true, true><<<ng, 256>>>(x, h0);

    // pass 1: inter, layer 0, relu
    // q: s <- W_ts[:C], t <- W_st[:C]; p: s <- W_st[C:], t <- W_ts[C:]
    k_dots<<<ng, 256>>>(h0, Wts, Wst + 128, Wst, Wts + 128);
    k_coef<false><<<ne, 256>>>();
    k_gather<false, true><<<ng, 256>>>(h0, h1);

    // pass 2: intra, layer 1, relu  (row 1 = offset 256)
    k_dots<<<ng, 256>>>(h1, Wss + 256, Wss + 256 + 128, Wtt + 256, Wtt + 256 + 128);
    k_coef<true><<<ne, 256>>>();
    k_gather<true, true><<<ng, 256>>>(h1, h0);

    // pass 3: inter, layer 1, no relu, write straight to d_out
    k_dots<<<ng, 256>>>(h0, Wts + 256, Wst + 256 + 128, Wst + 256, Wts + 256 + 128);
    k_coef<false><<<ne, 256>>>();
    k_gather<false, false><<<ng, 256>>>(h0, out);
}

// round 6
// speedup vs baseline: 2.0149x; 2.0149x over previous
#include <cuda_runtime.h>

#define S_NODES 8192
#define NN      8384
#define CH      128
#define BB      2
#define EE      262144

// ---------------- scratch (device globals; no allocation allowed) -----------
__device__ float  g_h0[BB * NN * CH];
__device__ float  g_h1[BB * NN * CH];
__device__ float  g_qA[BB * NN];
__device__ float  g_qB[BB * NN];
__device__ float2 g_pdA[BB * NN];      // (p, dinvI) packed per node
__device__ float2 g_pdB[BB * NN];
__device__ float  g_dinvI[BB * NN];    // gcn norm: rsqrt(intra_in_deg + 1)
__device__ float  g_dinvX[BB * NN];    // inter: 1/deg or 0
__device__ int    g_cntI[BB * NN];
__device__ int    g_cntX[BB * NN];
__device__ int    g_posI[BB * NN];
__device__ int    g_posX[BB * NN];
__device__ int    g_rpI[BB * (NN + 1)];
__device__ int    g_rpX[BB * (NN + 1)];
__device__ int    g_srcI[BB * EE];
__device__ int    g_srcX[BB * EE];

__device__ __forceinline__ float tanh_fast(float z) {
    float az = fabsf(z);
    float e  = __expf(2.0f * az);
    float r  = 1.0f - 2.0f / (e + 1.0f);
    return copysignf(r, z);
}

// ---------------- CSR build ------------------------------------------------
__global__ void k_zero() {
    int i = blockIdx.x * blockDim.x + threadIdx.x;
    if (i < BB * NN) { g_cntI[i] = 0; g_cntX[i] = 0; g_posI[i] = 0; g_posX[i] = 0; }
}

__global__ void k_hist(const int* __restrict__ ei) {
    int i = blockIdx.x * blockDim.x + threadIdx.x;
    if (i >= BB * EE) return;
    int b = i / EE, e = i - b * EE;
    int s = ei[b * 2 * EE + e];
    int d = ei[b * 2 * EE + EE + e];
    bool intra = (s < S_NODES) == (d < S_NODES);
    if (intra) atomicAdd(&g_cntI[b * NN + d], 1);
    else       atomicAdd(&g_cntX[b * NN + d], 1);
}

// one block per batch: exclusive scans of cntI and cntX over NN nodes + dinv
__global__ void k_scan() {
    __shared__ int shI[1024];
    __shared__ int shX[1024];
    __shared__ int carryI, carryX;
    int b = blockIdx.x;
    if (threadIdx.x == 0) { carryI = 0; carryX = 0; }
    __syncthreads();
    for (int base = 0; base < NN; base += 1024) {
        int i = base + threadIdx.x;
        int cI = 0, cX = 0;
        if (i < NN) {
            cI = g_cntI[b * NN + i];
            cX = g_cntX[b * NN + i];
        }
        shI[threadIdx.x] = cI;
        shX[threadIdx.x] = cX;
        __syncthreads();
        for (int off = 1; off < 1024; off <<= 1) {
            int tI = (threadIdx.x >= off) ? shI[threadIdx.x - off] : 0;
            int tX = (threadIdx.x >= off) ? shX[threadIdx.x - off] : 0;
            __syncthreads();
            shI[threadIdx.x] += tI;
            shX[threadIdx.x] += tX;
            __syncthreads();
        }
        if (i < NN) {
            g_rpI[b * (NN + 1) + i] = carryI + shI[threadIdx.x] - cI;  // exclusive
            g_rpX[b * (NN + 1) + i] = carryX + shX[threadIdx.x] - cX;
            g_dinvI[b * NN + i] = rsqrtf((float)(cI + 1));
            g_dinvX[b * NN + i] = (cX > 0) ? (1.0f / (float)cX) : 0.0f;
        }
        __syncthreads();
        if (threadIdx.x == 1023) { carryI += shI[1023]; carryX += shX[1023]; }
        __syncthreads();
    }
    if (threadIdx.x == 0) {
        g_rpI[b * (NN + 1) + NN] = carryI;
        g_rpX[b * (NN + 1) + NN] = carryX;
    }
}

__global__ void k_scatter(const int* __restrict__ ei) {
    int i = blockIdx.x * blockDim.x + threadIdx.x;
    if (i >= BB * EE) return;
    int b = i / EE, e = i - b * EE;
    int s = ei[b * 2 * EE + e];
    int d = ei[b * 2 * EE + EE + e];
    bool intra = (s < S_NODES) == (d < S_NODES);
    if (intra) {
        int pos = g_rpI[b * (NN + 1) + d] + atomicAdd(&g_posI[b * NN + d], 1);
        g_srcI[b * EE + pos] = s;
    } else {
        int pos = g_rpX[b * (NN + 1) + d] + atomicAdd(&g_posX[b * NN + d], 1);
        g_srcX[b * EE + pos] = s;
    }
}

// warp-per-node bitonic sort of each src segment (ascending) ->
// deterministic FP accumulation order (duplicate src values contribute
// bitwise-identical terms, so value-sort is a deterministic total order).
__global__ void k_sortW() {
    int wgid = (blockIdx.x * blockDim.x + threadIdx.x) >> 5;
    int lane = threadIdx.x & 31;
    if (wgid >= 2 * BB * NN) return;
    bool intra = wgid < BB * NN;
    int m = intra ? wgid : wgid - BB * NN;
    int b = m / NN, v = m - b * NN;
    const int* rp = intra ? g_rpI : g_rpX;
    int* srcs = (intra ? g_srcI : g_srcX) + b * EE;
    int beg = rp[b * (NN + 1) + v];
    int len = rp[b * (NN + 1) + v + 1] - beg;
    if (len <= 1) return;
    if (len <= 64) {
        int r0 = (lane < len)      ? srcs[beg + lane]      : 0x7fffffff;
        int r1 = (32 + lane < len) ? srcs[beg + 32 + lane] : 0x7fffffff;
        // bitonic sort of 64 elems: r0 = index lane, r1 = index 32+lane
        for (int k = 2; k <= 64; k <<= 1) {
            for (int j = k >> 1; j > 0; j >>= 1) {
                if (j == 32) {            // only for k=64, direction ascending
                    int lo = min(r0, r1), hi = max(r0, r1);
                    r0 = lo; r1 = hi;
                } else {
                    int o0 = __shfl_xor_sync(0xffffffffu, r0, j);
                    int o1 = __shfl_xor_sync(0xffffffffu, r1, j);
                    bool bit = (lane & j) != 0;
                    bool up0 = ((lane & k) == 0);
                    bool up1 = (((lane + 32) & k) == 0);
                    r0 = (bit != up0) ? min(r0, o0) : max(r0, o0);
                    r1 = (bit != up1) ? min(r1, o1) : max(r1, o1);
                }
            }
        }
        if (lane < len)      srcs[beg + lane]      = r0;
        if (32 + lane < len) srcs[beg + 32 + lane] = r1;
    } else if (lane == 0) {  // astronomically rare for random edges
        for (int i = 1; i < len; i++) {
            int key = srcs[beg + i]; int j = i - 1;
            while (j >= 0 && srcs[beg + j] > key) { srcs[beg + j + 1] = srcs[beg + j]; j--; }
            srcs[beg + j + 1] = key;
        }
    }
}

// ---------------- per-node attention dots (initial pass only) --------------
__global__ void k_dots(const float* __restrict__ x,
                       float* __restrict__ qout, float2* __restrict__ pdout,
                       const float* __restrict__ WaS, const float* __restrict__ WbS,
                       const float* __restrict__ WaT, const float* __restrict__ WbT) {
    int t = blockIdx.x * blockDim.x + threadIdx.x;
    int w = t >> 5, lane = t & 31;
    if (w >= BB * NN) return;
    int v = w % NN;
    const float* Wa = (v < S_NODES) ? WaS : WaT;
    const float* Wb = (v < S_NODES) ? WbS : WbT;
    float4 xv = ((const float4*)x)[w * 32 + lane];
    float4 wa = ((const float4*)Wa)[lane];
    float4 wb = ((const float4*)Wb)[lane];
    float qs = xv.x * wa.x + xv.y * wa.y + xv.z * wa.z + xv.w * wa.w;
    float ps = xv.x * wb.x + xv.y * wb.y + xv.z * wb.z + xv.w * wb.w;
    #pragma unroll
    for (int o = 16; o > 0; o >>= 1) {
        qs += __shfl_xor_sync(0xffffffffu, qs, o);
        ps += __shfl_xor_sync(0xffffffffu, ps, o);
    }
    if (lane == 0) { qout[w] = qs; pdout[w] = make_float2(ps, g_dinvI[w]); }
}

// ---------------- gather (warp per dst node) + fused next-pass dots --------
template <bool INTRA, bool RELU, bool DOTS>
__global__ void k_gather(const float* __restrict__ xin, float* __restrict__ xout,
                         const float* __restrict__ qin, const float2* __restrict__ pdin,
                         float* __restrict__ qout, float2* __restrict__ pdout,
                         const float* __restrict__ WaS, const float* __restrict__ WbS,
                         const float* __restrict__ WaT, const float* __restrict__ WbT) {
    int t = blockIdx.x * blockDim.x + threadIdx.x;
    int w = t >> 5, lane = t & 31;
    if (w >= BB * NN) return;
    int b = w / NN;
    int v = w - b * NN;
    const float4* __restrict__ x4 = (const float4*)xin;
    float4 xv = x4[w * 32 + lane];
    float4 acc = make_float4(0.f, 0.f, 0.f, 0.f);

    float qv = qin[w];
    float dv = INTRA ? g_dinvI[w] : g_dinvX[w];

    const int* rp = INTRA ? g_rpI : g_rpX;
    int beg = rp[b * (NN + 1) + v];
    int end = rp[b * (NN + 1) + v + 1];
    const int* __restrict__ srcs = (INTRA ? g_srcI : g_srcX) + b * EE;
    int bNN = b * NN;

    int e = beg;
    for (; e + 4 <= end; e += 4) {
        int s0 = bNN + srcs[e],     s1 = bNN + srcs[e + 1];
        int s2 = bNN + srcs[e + 2], s3 = bNN + srcs[e + 3];
        float2 p0 = pdin[s0], p1 = pdin[s1], p2 = pdin[s2], p3 = pdin[s3];
        float4 a0 = x4[s0 * 32 + lane];
        float4 a1 = x4[s1 * 32 + lane];
        float4 a2 = x4[s2 * 32 + lane];
        float4 a3 = x4[s3 * 32 + lane];
        float c0 = tanh_fast(qv + p0.x) * (INTRA ? dv * p0.y : dv);
        float c1 = tanh_fast(qv + p1.x) * (INTRA ? dv * p1.y : dv);
        float c2 = tanh_fast(qv + p2.x) * (INTRA ? dv * p2.y : dv);
        float c3 = tanh_fast(qv + p3.x) * (INTRA ? dv * p3.y : dv);
        acc.x += c0 * a0.x; acc.y += c0 * a0.y; acc.z += c0 * a0.z; acc.w += c0 * a0.w;
        acc.x += c1 * a1.x; acc.y += c1 * a1.y; acc.z += c1 * a1.z; acc.w += c1 * a1.w;
        acc.x += c2 * a2.x; acc.y += c2 * a2.y; acc.z += c2 * a2.z; acc.w += c2 * a2.w;
        acc.x += c3 * a3.x; acc.y += c3 * a3.y; acc.z += c3 * a3.z; acc.w += c3 * a3.w;
    }
    for (; e < end; e++) {
        int sn = bNN + srcs[e];
        float2 pe = pdin[sn];
        float ce = tanh_fast(qv + pe.x) * (INTRA ? dv * pe.y : dv);
        float4 xs = x4[sn * 32 + lane];
        acc.x += ce * xs.x; acc.y += ce * xs.y;
        acc.z += ce * xs.z; acc.w += ce * xs.w;
    }
    if (INTRA) {  // self loop: alpha_self = tanh(q+p), norm = 1/deg = dinv^2
        float cs = tanh_fast(qv + pdin[w].x) * dv * dv;
        acc.x += cs * xv.x; acc.y += cs * xv.y;
        acc.z += cs * xv.z; acc.w += cs * xv.w;
    }
    float4 o;
    o.x = xv.x + acc.x; o.y = xv.y + acc.y;
    o.z = xv.z + acc.z; o.w = xv.w + acc.w;
    if (RELU) {
        o.x = fmaxf(o.x, 0.f); o.y = fmaxf(o.y, 0.f);
        o.z = fmaxf(o.z, 0.f); o.w = fmaxf(o.w, 0.f);
    }
    ((float4*)xout)[w * 32 + lane] = o;

    if (DOTS) {  // q,p for the NEXT pass from the freshly computed output
        const float* Wa = (v < S_NODES) ? WaS : WaT;
        const float* Wb = (v < S_NODES) ? WbS : WbT;
        float4 wa = ((const float4*)Wa)[lane];
        float4 wb = ((const float4*)Wb)[lane];
        float qs = o.x * wa.x + o.y * wa.y + o.z * wa.z + o.w * wa.w;
        float ps = o.x * wb.x + o.y * wb.y + o.z * wb.z + o.w * wb.w;
        #pragma unroll
        for (int off = 16; off > 0; off >>= 1) {
            qs += __shfl_xor_sync(0xffffffffu, qs, off);
            ps += __shfl_xor_sync(0xffffffffu, ps, off);
        }
        if (lane == 0) { qout[w] = qs; pdout[w] = make_float2(ps, g_dinvI[w]); }
    }
}

// ---------------- launch ---------------------------------------------------
extern "C" void kernel_launch(void* const* d_in, const int* in_sizes, int n_in,
                              void* d_out, int out_size) {
    const float* x   = (const float*)d_in[0];
    const int*   ei  = (const int*)d_in[1];
    const float* Wss = (const float*)d_in[2];
    const float* Wtt = (const float*)d_in[3];
    const float* Wst = (const float*)d_in[4];
    const float* Wts = (const float*)d_in[5];
    float* out = (float*)d_out;

    float *h0, *h1, *qA, *qB;
    float2 *pdA, *pdB;
    cudaGetSymbolAddress((void**)&h0,  g_h0);
    cudaGetSymbolAddress((void**)&h1,  g_h1);
    cudaGetSymbolAddress((void**)&qA,  g_qA);
    cudaGetSymbolAddress((void**)&qB,  g_qB);
    cudaGetSymbolAddress((void**)&pdA, g_pdA);
    cudaGetSymbolAddress((void**)&pdB, g_pdB);

    // CSR build (depends only on edge_index; recomputed every call)
    k_zero<<<(BB * NN + 255) / 256, 256>>>();
    k_hist<<<(BB * EE + 255) / 256, 256>>>(ei);
    k_scan<<<BB, 1024>>>();
    k_scatter<<<(BB * EE + 255) / 256, 256>>>(ei);
    k_sortW<<<(2 * BB * NN * 32 + 255) / 256, 256>>>();

    int ng = (BB * NN * 32 + 255) / 256;   // warp-per-node grids

    // initial dots for pass 0 (intra L0): W_ss / W_tt row 0 -> set A
    k_dots<<<ng, 256>>>(x, qA, pdA, Wss, Wss + 128, Wtt, Wtt + 128);

    // pass 0: intra L0, relu; fused dots for pass 1 (inter L0) -> set B
    // inter dots: q: s <- W_ts[:C], t <- W_st[:C]; p: s <- W_st[C:], t <- W_ts[C:]
    k_gather<true, true, true><<<ng, 256>>>(x, h0, qA, pdA, qB, pdB,
                                            Wts, Wst + 128, Wst, Wts + 128);

    // pass 1: inter L0, relu; fused dots for pass 2 (intra L1, row 1) -> set A
    k_gather<false, true, true><<<ng, 256>>>(h0, h1, qB, pdB, qA, pdA,
                                             Wss + 256, Wss + 384, Wtt + 256, Wtt + 384);

    // pass 2: intra L1, relu; fused dots for pass 3 (inter L1) -> set B
    k_gather<true, true, true><<<ng, 256>>>(h1, h0, qA, pdA, qB, pdB,
                                            Wts + 256, Wst + 384, Wst + 256, Wts + 384);

    // pass 3: inter L1, no relu, write straight to d_out
    k_gather<false, false, false><<<ng, 256>>>(h0, out, qB, pdB, nullptr, nullptr,
                                               nullptr, nullptr, nullptr, nullptr);
}